// round 6
// baseline (speedup 1.0000x reference)
#include <cuda_runtime.h>
#include <cuda_fp16.h>
#include <cstdint>

#define NN 8192
#define SS 4
#define EE 262144
#define HH 64
#define FF 32

// ---------------- scratch (static device allocations; no cudaMalloc) --------
__device__ __align__(256) float  g_Ppart[4][NN][128];  // 16 MB split-K partials
__device__ __align__(256) __half g_Bh[128][NN];        // 2 MB: W1cat^T hi plane (fp16)
__device__ __align__(256) __half g_Bl[128][NN];        // 2 MB: W1cat^T lo plane (fp16)
__device__ __align__(256) float  g_sup1[SS][NN][HH];   // 8 MB
__device__ __align__(256) float  g_x1[NN][HH];         // 2 MB
__device__ __align__(256) float  g_sup2[SS][NN][FF];   // 4 MB
__device__ __align__(256) float  g_x2[NN][FF];         // 1 MB

// ---------------- fp16 split helpers ------------------------------------------
__device__ __forceinline__ void split_h(float x, __half& hi, __half& lo) {
    hi = __float2half_rn(x);
    lo = __float2half_rn(x - __half2float(hi));
}

__device__ __forceinline__ void mma_f16(float* c, const uint32_t* a, const uint32_t* b) {
    asm volatile(
        "mma.sync.aligned.m16n8k16.row.col.f32.f16.f16.f32 "
        "{%0,%1,%2,%3}, {%4,%5,%6,%7}, {%8,%9}, {%0,%1,%2,%3};"
        : "+f"(c[0]), "+f"(c[1]), "+f"(c[2]), "+f"(c[3])
        : "r"(a[0]), "r"(a[1]), "r"(a[2]), "r"(a[3]),
          "r"(b[0]), "r"(b[1]));
}

// ---------------- fused: zero accumulators + pre-split B ----------------------
// blocks [0, 1024): bsplit of W1 -> g_Bh/g_Bl (transposed [n][k] fp16 hi/lo)
// blocks [1024, 1792): zero g_x1, g_x2
__global__ void prep_kernel(const float* __restrict__ W1) {
    int blk = blockIdx.x;
    if (blk < 1024) {
        int lin = blk * 256 + threadIdx.x;   // over 128*2048
        int n = lin >> 11;
        int k = (lin & 2047) << 2;
        int b = n >> 6, h = n & 63;
        __half hh[4], ll[4];
#pragma unroll
        for (int q = 0; q < 4; q++) {
            float v = W1[((size_t)b * NN + k + q) * 64 + h];
            split_h(v, hh[q], ll[q]);
        }
        *reinterpret_cast<half2*>(&g_Bh[n][k])     = __halves2half2(hh[0], hh[1]);
        *reinterpret_cast<half2*>(&g_Bh[n][k + 2]) = __halves2half2(hh[2], hh[3]);
        *reinterpret_cast<half2*>(&g_Bl[n][k])     = __halves2half2(ll[0], ll[1]);
        *reinterpret_cast<half2*>(&g_Bl[n][k + 2]) = __halves2half2(ll[2], ll[3]);
    } else {
        int idx = (blk - 1024) * 256 + threadIdx.x;
        float4 z = make_float4(0.f, 0.f, 0.f, 0.f);
        const int n1 = NN * HH / 4;
        const int n2 = NN * FF / 4;
        if (idx < n1) {
            reinterpret_cast<float4*>(g_x1)[idx] = z;
        } else {
            int j = idx - n1;
            if (j < n2) reinterpret_cast<float4*>(g_x2)[j] = z;
        }
    }
}

// ---------------- layer-1 GEMM: P = feat[8192,8192] @ W1cat[8192,128] --------
// fp16x3 (hi/lo split) tensor-core GEMM via mma.sync.m16n8k16.
// 128x128 CTA tile, BK=32, split-K=4 (grid.y). 8 warps = 4(m) x 2(n);
// 2 CTAs/SM: all 256 CTAs resident -> no wave tail, staging bubbles overlapped.
__global__ void __launch_bounds__(256, 2)
gemm1_h3(const float* __restrict__ feat) {
    __shared__ __half Ah[128][40];   // A hi, [m][k], stride 40 halves (conflict-free)
    __shared__ __half Al[128][40];   // A lo
    __shared__ __half Bs_h[128][40]; // B hi, [n][k]
    __shared__ __half Bs_l[128][40]; // B lo

    const int tid  = threadIdx.x;
    const int lane = tid & 31;
    const int warp = tid >> 5;
    const int wm   = warp & 3;       // m slice: rows wm*32
    const int wn   = warp >> 2;      // n slice: cols wn*64
    const int g    = lane >> 2;      // 0..7
    const int t    = lane & 3;       // 0..3

    const int rowBase = blockIdx.x * 128;
    const int kBase   = blockIdx.y * 2048;

    float c[2][8][4];
#pragma unroll
    for (int i = 0; i < 2; i++)
#pragma unroll
        for (int j = 0; j < 8; j++)
#pragma unroll
            for (int q = 0; q < 4; q++) c[i][j][q] = 0.f;

    // prefetch registers
    float4 aR[4];          // A: 128x32 fp32 = 1024 float4, 4 per thread
    uint4  bHr[2], bLr[2]; // B: 128x32 halves per plane = 512 uint4, 2 per thread

    auto ldA = [&](int kk, int i) {
        int f = tid + (i << 8);
        int r = f >> 3, cc = (f & 7) << 2;
        return *reinterpret_cast<const float4*>(
            feat + (size_t)(rowBase + r) * NN + kBase + kk + cc);
    };
    auto ldBh = [&](int kk, int i) {
        int f = tid + (i << 8);
        int n = f >> 2, seg = (f & 3) << 3;
        return *reinterpret_cast<const uint4*>(&g_Bh[n][kBase + kk + seg]);
    };
    auto ldBl = [&](int kk, int i) {
        int f = tid + (i << 8);
        int n = f >> 2, seg = (f & 3) << 3;
        return *reinterpret_cast<const uint4*>(&g_Bl[n][kBase + kk + seg]);
    };

#pragma unroll
    for (int i = 0; i < 4; i++) aR[i] = ldA(0, i);
#pragma unroll
    for (int i = 0; i < 2; i++) { bHr[i] = ldBh(0, i); bLr[i] = ldBl(0, i); }

    for (int kk = 0; kk < 2048; kk += 32) {
        // regs -> smem (A split on the fly)
#pragma unroll
        for (int i = 0; i < 4; i++) {
            int f = tid + (i << 8);
            int r = f >> 3, cc = (f & 7) << 2;
            __half hx, lx, hy, ly, hz, lz, hw, lw;
            split_h(aR[i].x, hx, lx);
            split_h(aR[i].y, hy, ly);
            split_h(aR[i].z, hz, lz);
            split_h(aR[i].w, hw, lw);
            *reinterpret_cast<half2*>(&Ah[r][cc])     = __halves2half2(hx, hy);
            *reinterpret_cast<half2*>(&Ah[r][cc + 2]) = __halves2half2(hz, hw);
            *reinterpret_cast<half2*>(&Al[r][cc])     = __halves2half2(lx, ly);
            *reinterpret_cast<half2*>(&Al[r][cc + 2]) = __halves2half2(lz, lw);
        }
#pragma unroll
        for (int i = 0; i < 2; i++) {
            int f = tid + (i << 8);
            int n = f >> 2, seg = (f & 3) << 3;
            *reinterpret_cast<uint4*>(&Bs_h[n][seg]) = bHr[i];
            *reinterpret_cast<uint4*>(&Bs_l[n][seg]) = bLr[i];
        }
        __syncthreads();

        // prefetch next k-tile
        if (kk + 32 < 2048) {
#pragma unroll
            for (int i = 0; i < 4; i++) aR[i] = ldA(kk + 32, i);
#pragma unroll
            for (int i = 0; i < 2; i++) {
                bHr[i] = ldBh(kk + 32, i);
                bLr[i] = ldBl(kk + 32, i);
            }
        }

#pragma unroll
        for (int kc = 0; kc < 32; kc += 16) {
            uint32_t Ahf[2][4], Alf[2][4], Bhf[8][2], Blf[8][2];
#pragma unroll
            for (int i = 0; i < 2; i++) {
                const int r0 = wm * 32 + i * 16;
                Ahf[i][0] = *reinterpret_cast<const uint32_t*>(&Ah[r0 + g][kc + 2 * t]);
                Ahf[i][1] = *reinterpret_cast<const uint32_t*>(&Ah[r0 + 8 + g][kc + 2 * t]);
                Ahf[i][2] = *reinterpret_cast<const uint32_t*>(&Ah[r0 + g][kc + 8 + 2 * t]);
                Ahf[i][3] = *reinterpret_cast<const uint32_t*>(&Ah[r0 + 8 + g][kc + 8 + 2 * t]);
                Alf[i][0] = *reinterpret_cast<const uint32_t*>(&Al[r0 + g][kc + 2 * t]);
                Alf[i][1] = *reinterpret_cast<const uint32_t*>(&Al[r0 + 8 + g][kc + 2 * t]);
                Alf[i][2] = *reinterpret_cast<const uint32_t*>(&Al[r0 + g][kc + 8 + 2 * t]);
                Alf[i][3] = *reinterpret_cast<const uint32_t*>(&Al[r0 + 8 + g][kc + 8 + 2 * t]);
            }
#pragma unroll
            for (int j = 0; j < 8; j++) {
                const int c0 = wn * 64 + j * 8 + g;
                Bhf[j][0] = *reinterpret_cast<const uint32_t*>(&Bs_h[c0][kc + 2 * t]);
                Bhf[j][1] = *reinterpret_cast<const uint32_t*>(&Bs_h[c0][kc + 8 + 2 * t]);
                Blf[j][0] = *reinterpret_cast<const uint32_t*>(&Bs_l[c0][kc + 2 * t]);
                Blf[j][1] = *reinterpret_cast<const uint32_t*>(&Bs_l[c0][kc + 8 + 2 * t]);
            }
#pragma unroll
            for (int i = 0; i < 2; i++)
#pragma unroll
                for (int j = 0; j < 8; j++) {
                    mma_f16(c[i][j], Alf[i], Bhf[j]);   // low-order first
                    mma_f16(c[i][j], Ahf[i], Blf[j]);
                    mma_f16(c[i][j], Ahf[i], Bhf[j]);
                }
        }
        __syncthreads();
    }

    // write split-K partial
    const int kslice = blockIdx.y;
#pragma unroll
    for (int i = 0; i < 2; i++) {
        const int row = rowBase + wm * 32 + i * 16 + g;
#pragma unroll
        for (int j = 0; j < 8; j++) {
            const int col = wn * 64 + j * 8 + 2 * t;
            *reinterpret_cast<float2*>(&g_Ppart[kslice][row][col]) =
                make_float2(c[i][j][0], c[i][j][1]);
            *reinterpret_cast<float2*>(&g_Ppart[kslice][row + 8][col]) =
                make_float2(c[i][j][2], c[i][j][3]);
        }
    }
}

// ---------------- combine split-K partials + basis coefficients -> sup1 ------
__global__ void sup1_kernel(const float* __restrict__ Wc1) {
    int idx = blockIdx.x * blockDim.x + threadIdx.x;
    if (idx >= NN * HH) return;
    int n = idx >> 6, h = idx & 63;
    float p0 = g_Ppart[0][n][h] + g_Ppart[1][n][h] +
               g_Ppart[2][n][h] + g_Ppart[3][n][h];
    float p1 = g_Ppart[0][n][64 + h] + g_Ppart[1][n][64 + h] +
               g_Ppart[2][n][64 + h] + g_Ppart[3][n][64 + h];
#pragma unroll
    for (int s = 0; s < 4; s++)
        g_sup1[s][n][h] = Wc1[s * 2] * p0 + Wc1[s * 2 + 1] * p1;
}

// ---------------- layer-1 aggregation: 16 threads/edge, red.v4 ---------------
__global__ void agg1_kernel(const int* __restrict__ src,
                            const int* __restrict__ dst,
                            const float* __restrict__ w) {
    int idx = blockIdx.x * blockDim.x + threadIdx.x;
    int h4 = idx & 15;
    int e  = idx >> 4;
    int s  = e >> 18;
    int es = __ldg(src + e);
    int ed = __ldg(dst + e);
    float ww = __ldg(w + e);
    const float4 v = *reinterpret_cast<const float4*>(&g_sup1[s][es][h4 * 4]);
    float x0 = v.x * ww, x1 = v.y * ww, x2 = v.z * ww, x3 = v.w * ww;
    float* o = &g_x1[ed][h4 * 4];
    asm volatile("red.global.add.v4.f32 [%0], {%1, %2, %3, %4};"
                 :: "l"(o), "f"(x0), "f"(x1), "f"(x2), "f"(x3) : "memory");
}

// ---------------- layer 2 dense: sup2[s] = tanh(x1) @ (Wc2[s,.]·W2) ----------
__global__ void sup2_kernel(const float* __restrict__ W2,
                            const float* __restrict__ Wc2) {
    __shared__ float V2s[4][64][32];
    __shared__ float x1s[64][64];
    int tid   = threadIdx.x;
    int node0 = blockIdx.x * 64;

    for (int i = tid; i < 4 * 64 * 32; i += 256) {
        int s = i >> 11, k = (i >> 5) & 63, f = i & 31;
        V2s[s][k][f] = Wc2[2 * s] * W2[k * 32 + f] +
                       Wc2[2 * s + 1] * W2[64 * 32 + k * 32 + f];
    }
    for (int i = tid; i < 64 * 64; i += 256) {
        int n = i >> 6, k = i & 63;
        x1s[n][k] = tanhf(g_x1[node0 + n][k]);
    }
    __syncthreads();

    int q = tid & 3;
    int n = tid >> 2;
    float acc[32];
#pragma unroll
    for (int f = 0; f < 32; f++) acc[f] = 0.f;
#pragma unroll 4
    for (int k = 0; k < 64; k++) {
        float a = x1s[n][k];
#pragma unroll
        for (int f = 0; f < 32; f++) acc[f] += a * V2s[q][k][f];
    }
    float4* orow = reinterpret_cast<float4*>(&g_sup2[q][node0 + n][0]);
#pragma unroll
    for (int f4 = 0; f4 < 8; f4++)
        orow[f4] = make_float4(acc[f4 * 4], acc[f4 * 4 + 1],
                               acc[f4 * 4 + 2], acc[f4 * 4 + 3]);
}

// ---------------- layer-2 aggregation: 8 threads/edge, red.v4 ----------------
__global__ void agg2_kernel(const int* __restrict__ src,
                            const int* __restrict__ dst,
                            const float* __restrict__ w) {
    int idx = blockIdx.x * blockDim.x + threadIdx.x;
    int h4 = idx & 7;
    int e  = idx >> 3;
    int s  = e >> 18;
    int es = __ldg(src + e);
    int ed = __ldg(dst + e);
    float ww = __ldg(w + e);
    const float4 v = *reinterpret_cast<const float4*>(&g_sup2[s][es][h4 * 4]);
    float x0 = v.x * ww, x1 = v.y * ww, x2 = v.z * ww, x3 = v.w * ww;
    float* o = &g_x2[ed][h4 * 4];
    asm volatile("red.global.add.v4.f32 [%0], {%1, %2, %3, %4};"
                 :: "l"(o), "f"(x0), "f"(x1), "f"(x2), "f"(x3) : "memory");
}

// ---------------- classifier: out = tanh(x2) @ Wclf + bclf -------------------
__global__ void clf_kernel(const float* __restrict__ Wclf,
                           const float* __restrict__ bclf,
                           float* __restrict__ out) {
    int n = blockIdx.x * blockDim.x + threadIdx.x;
    if (n >= NN) return;
    float acc0 = bclf[0], acc1 = bclf[1];
#pragma unroll
    for (int f = 0; f < 32; f++) {
        float x = tanhf(g_x2[n][f]);
        acc0 += x * Wclf[f * 2 + 0];
        acc1 += x * Wclf[f * 2 + 1];
    }
    out[n * 2 + 0] = acc0;
    out[n * 2 + 1] = acc1;
}

// -----------------------------------------------------------------------------
extern "C" void kernel_launch(void* const* d_in, const int* in_sizes, int n_in,
                              void* d_out, int out_size) {
    const float* feat   = (const float*)d_in[0];
    const float* edge_w = (const float*)d_in[1];
    const float* W1     = (const float*)d_in[2];
    const float* Wc1    = (const float*)d_in[3];
    const float* W2     = (const float*)d_in[4];
    const float* Wc2    = (const float*)d_in[5];
    const float* Wclf   = (const float*)d_in[6];
    const float* bclf   = (const float*)d_in[7];
    const int*   esrc   = (const int*)d_in[8];
    const int*   edst   = (const int*)d_in[9];
    float* out = (float*)d_out;

    prep_kernel<<<1792, 256>>>(W1);
    gemm1_h3<<<dim3(64, 4), 256>>>(feat);
    sup1_kernel<<<(NN * HH) / 256, 256>>>(Wc1);
    agg1_kernel<<<(SS * EE * 16) / 256, 256>>>(esrc, edst, edge_w);
    sup2_kernel<<<NN / 64, 256>>>(W2, Wc2);
    agg2_kernel<<<(SS * EE * 8) / 256, 256>>>(esrc, edst, edge_w);
    clf_kernel<<<NN / 256, 256>>>(Wclf, bclf, out);
}